// round 15
// baseline (speedup 1.0000x reference)
#include <cuda_runtime.h>
#include <cuda_fp16.h>
#include <math.h>
#include <stdint.h>

// ---------------- problem constants ----------------
#define NEMBD   2048
#define NH      16
#define DH      128
#define BATCH   2
#define SEQ     2048
#define MROWS   (BATCH*SEQ)     // 4096
#define QKV_N   (3*NEMBD)       // 6144
#define BHN     (BATCH*NH)      // 32

// ---------------- scratch (device globals, no runtime allocs) ----------------
__device__ __half g_qh[(size_t)BHN*SEQ*DH];
__device__ __half g_kh[(size_t)BHN*SEQ*DH];
__device__ __half g_vh[(size_t)BHN*SEQ*DH];
__device__ __half g_xh[(size_t)MROWS*NEMBD];
__device__ __half g_wq[(size_t)QKV_N*NEMBD];
__device__ __half g_wp[(size_t)NEMBD*NEMBD];
__device__ __half g_yh[(size_t)MROWS*NEMBD];
__device__ float g_cos[SEQ*64];
__device__ float g_sin[SEQ*64];

// ================= common asm helpers =================
#define MMA16816(d, a0, a1, a2, a3, b0, b1)                                \
    asm volatile(                                                          \
        "mma.sync.aligned.m16n8k16.row.col.f32.f16.f16.f32 "               \
        "{%0,%1,%2,%3}, {%4,%5,%6,%7}, {%8,%9}, {%0,%1,%2,%3};"            \
        : "+f"((d)[0]), "+f"((d)[1]), "+f"((d)[2]), "+f"((d)[3])           \
        : "r"(a0), "r"(a1), "r"(a2), "r"(a3), "r"(b0), "r"(b1))

#define LDSM_X4(r0, r1, r2, r3, addr)                                       \
    asm volatile("ldmatrix.sync.aligned.m8n8.x4.shared.b16 "                \
                 "{%0,%1,%2,%3}, [%4];"                                     \
                 : "=r"(r0), "=r"(r1), "=r"(r2), "=r"(r3) : "r"(addr))

#define LDSM_X4T(r0, r1, r2, r3, addr)                                      \
    asm volatile("ldmatrix.sync.aligned.m8n8.x4.trans.shared.b16 "          \
                 "{%0,%1,%2,%3}, [%4];"                                     \
                 : "=r"(r0), "=r"(r1), "=r"(r2), "=r"(r3) : "r"(addr))

#define CP_ASYNC16(dst, src)                                                \
    asm volatile("cp.async.cg.shared.global [%0], [%1], 16;"                \
                 :: "r"(dst), "l"(src))
#define CP_COMMIT() asm volatile("cp.async.commit_group;" ::: "memory")
#define CP_WAIT1()  asm volatile("cp.async.wait_group 1;" ::: "memory")
#define CP_WAIT0()  asm volatile("cp.async.wait_group 0;" ::: "memory")

__device__ __forceinline__ uint32_t smem_u32(const void* p) {
    uint32_t a;
    asm("{ .reg .u64 t; cvta.to.shared.u64 t, %1; cvt.u32.u64 %0, t; }"
        : "=r"(a) : "l"(p));
    return a;
}

__device__ __forceinline__ uint32_t fp16_pack2(float x, float y) {
    __half2 h = __floats2half2_rn(x, y);
    return *(uint32_t*)&h;
}

// ================= RoPE tables (fp64 angles) =================
__global__ void rope_table_kernel(float* gcos, float* gsin) {
    int idx = blockIdx.x * blockDim.x + threadIdx.x;
    if (idx >= SEQ * 64) return;
    int t = idx >> 6;
    int i = idx & 63;
    double freq = exp(-((double)(2 * i) / 128.0) * log(10000.0));
    double ang = (double)t * freq;
    gcos[idx] = (float)cos(ang);
    gsin[idx] = (float)sin(ang);
}

// ============ fused fp32 -> fp16 convert for x, w_qkv, w_proj ================
#define CVT_N1 ((long long)MROWS * NEMBD / 4)
#define CVT_N2 ((long long)QKV_N * NEMBD / 4)
#define CVT_N3 ((long long)NEMBD * NEMBD / 4)
#define CVT_TOT (CVT_N1 + CVT_N2 + CVT_N3)

__global__ void cvt_all_kernel(const float* __restrict__ x,
                               const float* __restrict__ wq32,
                               const float* __restrict__ wp32,
                               __half* __restrict__ xh,
                               __half* __restrict__ wq,
                               __half* __restrict__ wp) {
    long long i = (long long)blockIdx.x * blockDim.x + threadIdx.x;
    if (i >= CVT_TOT) return;
    const float* src;
    __half* dst;
    long long j;
    if (i < CVT_N1)               { src = x;    dst = xh; j = i; }
    else if (i < CVT_N1 + CVT_N2) { src = wq32; dst = wq; j = i - CVT_N1; }
    else                          { src = wp32; dst = wp; j = i - CVT_N1 - CVT_N2; }
    float4 v = *(const float4*)(src + j * 4);
    *(uint2*)(dst + j * 4) = make_uint2(fp16_pack2(v.x, v.y), fp16_pack2(v.z, v.w));
}

// ================= GEMM tiling constants =================
#define SLD 40
#define RLD 132

// ===== QKV GEMM + fused RoPE: tile 64x128, 128 thr, 3 CTAs/SM ================
#define QARR_A 5120                 // 64 rows * 80 B
#define QARR_W 10240                // 128 rows * 80 B
#define QSTG  (QARR_A + QARR_W)     // 15360 B per stage
#define QKV_SMEM (2*QSTG)           // 30720 B  (epilogue stage 32x132 f32 = 16896 B fits)

__global__ __launch_bounds__(128, 3)
void gemm_qkv_rope_kernel(const __half* __restrict__ A,
                          const __half* __restrict__ W,
                          const float* __restrict__ gcos,
                          const float* __restrict__ gsin,
                          __half* __restrict__ qh,
                          __half* __restrict__ kh,
                          __half* __restrict__ vh) {
    extern __shared__ char gsm[];
    const uint32_t sb = smem_u32(gsm);
    const int K = NEMBD;

    const int tid  = threadIdx.x;
    const int warp = tid >> 5, lane = tid & 31;
    const int g = lane >> 2, t = lane & 3;
    const int wm = warp & 1, wn = warp >> 1;     // 2x2 warps; warp tile 32x64
    const int m0 = blockIdx.y * 64;
    const int n0 = blockIdx.x * 128;
    const int NT = K / 32;

    float acc[2][8][4];
#pragma unroll
    for (int mf = 0; mf < 2; mf++)
#pragma unroll
        for (int nf = 0; nf < 8; nf++)
#pragma unroll
            for (int r = 0; r < 4; r++) acc[mf][nf][r] = 0.0f;

    auto prefetch = [&](int s, int kt) {
#pragma unroll
        for (int it = 0; it < 6; it++) {
            int i = tid + it * 128;        // 0..767 : 256 A-chunks + 512 W-chunks
            const __half* src;
            uint32_t dst;
            if (i < 256) {
                int row = i >> 2, ch = i & 3;
                src = A + (size_t)(m0 + row) * K + kt * 32 + ch * 8;
                dst = sb + (uint32_t)(s * QSTG + row * 80 + ch * 16);
            } else {
                int j = i - 256;
                int row = j >> 2, ch = j & 3;
                src = W + (size_t)(n0 + row) * K + kt * 32 + ch * 8;
                dst = sb + (uint32_t)(s * QSTG + QARR_A + row * 80 + ch * 16);
            }
            CP_ASYNC16(dst, src);
        }
    };

    prefetch(0, 0);
    CP_COMMIT();

    for (int kt = 0; kt < NT; kt++) {
        if (kt + 1 < NT) {
            prefetch((kt + 1) & 1, kt + 1);
            CP_COMMIT();
            CP_WAIT1();
        } else {
            CP_WAIT0();
        }
        __syncthreads();

        const __half* As = (const __half*)(gsm + (size_t)(kt & 1) * QSTG);
        const __half* Ws = As + QARR_A / 2;

#pragma unroll
        for (int kk = 0; kk < 32; kk += 16) {
            uint32_t a[2][4];
#pragma unroll
            for (int mf = 0; mf < 2; mf++) {
                int r = wm * 32 + mf * 16 + g;
                const __half* p = &As[r * SLD + kk + 2 * t];
                a[mf][0] = *(const uint32_t*)p;
                a[mf][1] = *(const uint32_t*)(p + 8 * SLD);
                a[mf][2] = *(const uint32_t*)(p + 8);
                a[mf][3] = *(const uint32_t*)(p + 8 * SLD + 8);
            }
#pragma unroll
            for (int nf = 0; nf < 8; nf++) {
                const __half* p = &Ws[(wn * 64 + nf * 8 + g) * SLD + kk + 2 * t];
                uint32_t w0 = *(const uint32_t*)p;
                uint32_t w1 = *(const uint32_t*)(p + 8);
#pragma unroll
                for (int mf = 0; mf < 2; mf++)
                    MMA16816(acc[mf][nf], a[mf][0], a[mf][1], a[mf][2], a[mf][3], w0, w1);
            }
        }
        __syncthreads();
    }

    // ---------------- fused epilogue ----------------
    const int part = n0 >> 11;          // 0=q, 1=k, 2=v
    const int h    = (n0 & 2047) >> 7;

    if (part == 2) {
        // V: no RoPE, direct fp16 write in [bh, t, d]
#pragma unroll
        for (int mf = 0; mf < 2; mf++) {
            int m = m0 + wm * 32 + mf * 16 + g;
            int b0 = m >> 11, t0 = m & 2047;
            int b1 = (m + 8) >> 11, t1 = (m + 8) & 2047;
            size_t o0 = ((size_t)(b0 * 16 + h) * SEQ + t0) * DH;
            size_t o1 = ((size_t)(b1 * 16 + h) * SEQ + t1) * DH;
#pragma unroll
            for (int nf = 0; nf < 8; nf++) {
                int d = wn * 64 + nf * 8 + 2 * t;
                *(uint32_t*)(vh + o0 + d) = fp16_pack2(acc[mf][nf][0], acc[mf][nf][1]);
                *(uint32_t*)(vh + o1 + d) = fp16_pack2(acc[mf][nf][2], acc[mf][nf][3]);
            }
        }
    } else {
        // Q/K: stage fp32 in two 32-row halves, apply RoPE, write fp16
        float* stage = (float*)gsm;
        const float qscale = 0.08838834764831845f;
#pragma unroll
        for (int half = 0; half < 2; half++) {
            __syncthreads();
            if (wm == half) {
#pragma unroll
                for (int mf = 0; mf < 2; mf++) {
                    int lr0 = mf * 16 + g;     // 0..31 within the half
#pragma unroll
                    for (int nf = 0; nf < 8; nf++) {
                        int col = wn * 64 + nf * 8 + 2 * t;
                        stage[lr0 * RLD + col]           = acc[mf][nf][0];
                        stage[lr0 * RLD + col + 1]       = acc[mf][nf][1];
                        stage[(lr0 + 8) * RLD + col]     = acc[mf][nf][2];
                        stage[(lr0 + 8) * RLD + col + 1] = acc[mf][nf][3];
                    }
                }
            }
            __syncthreads();
#pragma unroll
            for (int it = 0; it < 32; it++) {
                int idx = tid + it * 128;
                int lr = idx >> 7, d = idx & 127;
                int m = m0 + half * 32 + lr;
                int trow = m & 2047, b = m >> 11;
                float val = stage[lr * RLD + d];
                float par = stage[lr * RLD + (d ^ 64)];
                int ci = d & 63;
                float c  = gcos[trow * 64 + ci];
                float sn = gsin[trow * 64 + ci];
                float rot = (d < 64) ? -par : par;
                float outv = val * c + rot * sn;
                size_t o = ((size_t)(b * 16 + h) * SEQ + trow) * DH + d;
                if (part == 0) qh[o] = __float2half_rn(outv * qscale);
                else           kh[o] = __float2half_rn(outv);
            }
        }
    }
}

// ===== plain fp16 HMMA GEMM (output projection): 128x128, 256 thr ===========
#define GARR 10240
#define GSTG (2*GARR)
#define GEMM_SMEM (2*GSTG)

__global__ __launch_bounds__(256, 2)
void gemm_fp16_kernel(const __half* __restrict__ A,
                      const __half* __restrict__ W,
                      float* __restrict__ C, int M, int N, int K) {
    extern __shared__ char gsm[];
    const uint32_t sb = smem_u32(gsm);

    const int tid  = threadIdx.x;
    const int warp = tid >> 5, lane = tid & 31;
    const int g = lane >> 2, t = lane & 3;
    const int wm = warp & 3, wn = warp >> 2;
    const int m0 = blockIdx.y * 128;
    const int n0 = blockIdx.x * 128;
    const int NT = K / 32;

    float acc[2][8][4];
#pragma unroll
    for (int mf = 0; mf < 2; mf++)
#pragma unroll
        for (int nf = 0; nf < 8; nf++)
#pragma unroll
            for (int r = 0; r < 4; r++) acc[mf][nf][r] = 0.0f;

    auto prefetch = [&](int s, int kt) {
#pragma unroll
        for (int it = 0; it < 4; it++) {
            int i = tid + it * 256;
            int arr = i >> 9;
            int row = (i >> 2) & 127;
            int ch  = i & 3;
            const __half* src =
                (arr == 0) ? A + (size_t)(m0 + row) * K :
                             W + (size_t)(n0 + row) * K;
            src += kt * 32 + ch * 8;
            uint32_t dst = sb + (uint32_t)(s * GSTG + arr * GARR + row * 80 + ch * 16);
            CP_ASYNC16(dst, src);
        }
    };

    prefetch(0, 0);
    CP_COMMIT();

    for (int kt = 0; kt < NT; kt++) {
        if (kt + 1 < NT) {
            prefetch((kt + 1) & 1, kt + 1);
            CP_COMMIT();
            CP_WAIT1();
        } else {
            CP_WAIT0();
        }
        __syncthreads();

        const __half* As = (const __half*)(gsm + (size_t)(kt & 1) * GSTG);
        const __half* Ws = As + GARR / 2;

#pragma unroll
        for (int kk = 0; kk < 32; kk += 16) {
            uint32_t a[2][4];
#pragma unroll
            for (int mf = 0; mf < 2; mf++) {
                int r = wm * 32 + mf * 16 + g;
                const __half* p = &As[r * SLD + kk + 2 * t];
                a[mf][0] = *(const uint32_t*)p;
                a[mf][1] = *(const uint32_t*)(p + 8 * SLD);
                a[mf][2] = *(const uint32_t*)(p + 8);
                a[mf][3] = *(const uint32_t*)(p + 8 * SLD + 8);
            }
#pragma unroll
            for (int nf = 0; nf < 8; nf++) {
                const __half* p = &Ws[(wn * 64 + nf * 8 + g) * SLD + kk + 2 * t];
                uint32_t w0 = *(const uint32_t*)p;
                uint32_t w1 = *(const uint32_t*)(p + 8);
#pragma unroll
                for (int mf = 0; mf < 2; mf++)
                    MMA16816(acc[mf][nf], a[mf][0], a[mf][1], a[mf][2], a[mf][3], w0, w1);
            }
        }
        __syncthreads();
    }

#pragma unroll
    for (int mf = 0; mf < 2; mf++) {
        int r0 = m0 + wm * 32 + mf * 16 + g;
#pragma unroll
        for (int nf = 0; nf < 8; nf++) {
            int col = n0 + wn * 64 + nf * 8 + 2 * t;
            float* p0 = C + (size_t)r0 * N + col;
            float* p1 = C + (size_t)(r0 + 8) * N + col;
            *(float2*)p0 = make_float2(acc[mf][nf][0], acc[mf][nf][1]);
            *(float2*)p1 = make_float2(acc[mf][nf][2], acc[mf][nf][3]);
        }
    }
}

// ============ flash attention: FBQ=64, 128 threads (R14-proven) ==============
#define FBQ 64
#define FBK 64
#define FLD 136
#define ARRB 17408u
#define STG_B (2 * 17408)
#define FA2_SMEM (2 * STG_B)

__global__ __launch_bounds__(128, 2)
void flash_mma_kernel(const __half* __restrict__ Qg,
                      const __half* __restrict__ KH,
                      const __half* __restrict__ VH,
                      __half* __restrict__ Yh) {
    extern __shared__ char smc[];
    const uint32_t sbase = smem_u32(smc);

    const int tid  = threadIdx.x;
    const int w    = tid >> 5, lane = tid & 31;
    const int g    = lane >> 2, t = lane & 3;
    const int qi   = gridDim.x - 1 - blockIdx.x;
    const int bh   = blockIdx.y;
    const int qbase = qi * FBQ;

    const size_t bhoff = (size_t)bh * SEQ * DH;

    uint32_t qf[8][4];
    {
        const __half* q0 = Qg + bhoff + (size_t)(qbase + w * 16 + g) * DH;
        const __half* q1 = q0 + 8 * DH;
#pragma unroll
        for (int kf = 0; kf < 8; kf++) {
            qf[kf][0] = *(const uint32_t*)(q0 + 16 * kf + 2 * t);
            qf[kf][1] = *(const uint32_t*)(q1 + 16 * kf + 2 * t);
            qf[kf][2] = *(const uint32_t*)(q0 + 16 * kf + 2 * t + 8);
            qf[kf][3] = *(const uint32_t*)(q1 + 16 * kf + 2 * t + 8);
        }
    }

    const uint32_t lmK = (uint32_t)(((lane & 7) * FLD + (lane >> 3) * 8) * 2);
    const uint32_t lmV = (uint32_t)((((lane & 7) + ((lane >> 3) & 1) * 8) * FLD
                                     + (lane >> 4) * 8) * 2);

    float m0r = -1e30f, m1r = -1e30f, l0r = 0.0f, l1r = 0.0f;
    float o[16][4];
#pragma unroll
    for (int nf = 0; nf < 16; nf++)
#pragma unroll
        for (int r = 0; r < 4; r++) o[nf][r] = 0.0f;

    const int nkt = qi + 1;

    auto prefetch = [&](int s, int kt) {
        const int kb = kt * FBK;
        const __half* srcs[2] = { KH + bhoff + (size_t)kb * DH,
                                  VH + bhoff + (size_t)kb * DH };
        uint32_t dst0 = sbase + (uint32_t)s * STG_B;
#pragma unroll
        for (int it = 0; it < 16; it++) {
            int i = tid + it * 128;
            int arr = i >> 10, key = (i >> 4) & 63, ch = i & 15;
            const __half* src = srcs[arr] + key * DH + ch * 8;
            uint32_t dst = dst0 + (uint32_t)(arr * ARRB + key * 272 + ch * 16);
            CP_ASYNC16(dst, src);
        }
    };

    prefetch(0, 0);
    CP_COMMIT();

    for (int kt = 0; kt < nkt; kt++) {
        if (kt + 1 < nkt) {
            prefetch((kt + 1) & 1, kt + 1);
            CP_COMMIT();
            CP_WAIT1();
        } else {
            CP_WAIT0();
        }
        __syncthreads();

        const int kbase = kt * FBK;
        {
            const uint32_t stg = sbase + (uint32_t)(kt & 1) * STG_B;

            float s[8][4];
#pragma unroll
            for (int nf = 0; nf < 8; nf++)
#pragma unroll
                for (int r = 0; r < 4; r++) s[nf][r] = 0.0f;

#pragma unroll
            for (int kf2 = 0; kf2 < 4; kf2++) {
#pragma unroll
                for (int nf = 0; nf < 8; nf++) {
                    uint32_t off = (uint32_t)((nf * 8 * FLD + kf2 * 32) * 2);
                    uint32_t k0, k1, k2, k3;
                    LDSM_X4(k0, k1, k2, k3, stg + lmK + off);
                    MMA16816(s[nf], qf[2*kf2][0], qf[2*kf2][1], qf[2*kf2][2], qf[2*kf2][3], k0, k1);
                    MMA16816(s[nf], qf[2*kf2+1][0], qf[2*kf2+1][1], qf[2*kf2+1][2], qf[2*kf2+1][3], k2, k3);
                }
            }

            const int row0 = qbase + w * 16 + g;
            const int row1 = row0 + 8;
            if (kbase + FBK - 1 > qbase + w * 16) {
#pragma unroll
                for (int nf = 0; nf < 8; nf++) {
                    int c0 = kbase + 8 * nf + 2 * t;
                    if (c0 > row0)     s[nf][0] = -1e30f;
                    if (c0 + 1 > row0) s[nf][1] = -1e30f;
                    if (c0 > row1)     s[nf][2] = -1e30f;
                    if (c0 + 1 > row1) s[nf][3] = -1e30f;
                }
            }

            float mx0 = -1e30f, mx1 = -1e30f;
#pragma unroll
            for (int nf = 0; nf < 8; nf++) {
                mx0 = fmaxf(mx0, fmaxf(s[nf][0], s[nf][1]));
                mx1 = fmaxf(mx1, fmaxf(s[nf][2], s[nf][3]));
            }
            mx0 = fmaxf(mx0, __shfl_xor_sync(0xffffffffu, mx0, 1));
            mx0 = fmaxf(mx0, __shfl_xor_sync(0xffffffffu, mx0, 2));
            mx1 = fmaxf(mx1, __shfl_xor_sync(0xffffffffu, mx1, 1));
            mx1 = fmaxf(mx1, __shfl_xor_sync(0xffffffffu, mx1, 2));
            float mn0 = fmaxf(m0r, mx0), mn1 = fmaxf(m1r, mx1);
            float a0 = __expf(m0r - mn0), a1 = __expf(m1r - mn1);
            m0r = mn0; m1r = mn1;
            float rs0 = 0.0f, rs1 = 0.0f;
#pragma unroll
            for (int nf = 0; nf < 8; nf++) {
                s[nf][0] = __expf(s[nf][0] - mn0);
                s[nf][1] = __expf(s[nf][1] - mn0);
                s[nf][2] = __expf(s[nf][2] - mn1);
                s[nf][3] = __expf(s[nf][3] - mn1);
                rs0 += s[nf][0] + s[nf][1];
                rs1 += s[nf][2] + s[nf][3];
            }
            rs0 += __shfl_xor_sync(0xffffffffu, rs0, 1);
            rs0 += __shfl_xor_sync(0xffffffffu, rs0, 2);
            rs1 += __shfl_xor_sync(0xffffffffu, rs1, 1);
            rs1 += __shfl_xor_sync(0xffffffffu, rs1, 2);
            l0r = l0r * a0 + rs0;
            l1r = l1r * a1 + rs1;
#pragma unroll
            for (int nf = 0; nf < 16; nf++) {
                o[nf][0] *= a0; o[nf][1] *= a0;
                o[nf][2] *= a1; o[nf][3] *= a1;
            }

#pragma unroll
            for (int kf = 0; kf < 4; kf++) {
                uint32_t ph[4];
                ph[0] = fp16_pack2(s[2*kf][0],   s[2*kf][1]);
                ph[1] = fp16_pack2(s[2*kf][2],   s[2*kf][3]);
                ph[2] = fp16_pack2(s[2*kf+1][0], s[2*kf+1][1]);
                ph[3] = fp16_pack2(s[2*kf+1][2], s[2*kf+1][3]);
                uint32_t voff = (uint32_t)((kf * 16 * FLD) * 2);
#pragma unroll
                for (int nf2 = 0; nf2 < 8; nf2++) {
                    uint32_t off = voff + (uint32_t)(nf2 * 32);
                    uint32_t v0, v1, v2, v3;
                    LDSM_X4T(v0, v1, v2, v3, stg + ARRB + lmV + off);
                    MMA16816(o[2*nf2],   ph[0], ph[1], ph[2], ph[3], v0, v1);
                    MMA16816(o[2*nf2+1], ph[0], ph[1], ph[2], ph[3], v2, v3);
                }
            }
        }
        __syncthreads();
    }

    const int b = bh >> 4, h = bh & 15;
    const int row0 = qbase + w * 16 + g;
    const float inv0 = 1.0f / l0r, inv1 = 1.0f / l1r;
    size_t y0off = ((size_t)(b * SEQ + row0)) * NEMBD + h * DH;
    size_t y1off = ((size_t)(b * SEQ + row0 + 8)) * NEMBD + h * DH;
#pragma unroll
    for (int nf = 0; nf < 16; nf++) {
        int col = 8 * nf + 2 * t;
        *(uint32_t*)(Yh + y0off + col) = fp16_pack2(o[nf][0] * inv0, o[nf][1] * inv0);
        *(uint32_t*)(Yh + y1off + col) = fp16_pack2(o[nf][2] * inv1, o[nf][3] * inv1);
    }
}

// ================= launch =====================================================
extern "C" void kernel_launch(void* const* d_in, const int* in_sizes, int n_in,
                              void* d_out, int out_size) {
    const float* x      = (const float*)d_in[0];
    const float* w_qkv  = (const float*)d_in[1];
    const float* w_proj = (const float*)d_in[2];
    float* out = (float*)d_out;

    float *gc, *gs;
    __half *qh, *kh, *vh, *xh, *wq, *wp, *yh;
    cudaGetSymbolAddress((void**)&qh, g_qh);
    cudaGetSymbolAddress((void**)&kh, g_kh);
    cudaGetSymbolAddress((void**)&vh, g_vh);
    cudaGetSymbolAddress((void**)&xh, g_xh);
    cudaGetSymbolAddress((void**)&wq, g_wq);
    cudaGetSymbolAddress((void**)&wp, g_wp);
    cudaGetSymbolAddress((void**)&yh, g_yh);
    cudaGetSymbolAddress((void**)&gc, g_cos);
    cudaGetSymbolAddress((void**)&gs, g_sin);

    // 1) RoPE tables + fused operand conversions
    rope_table_kernel<<<(SEQ * 64 + 255) / 256, 256>>>(gc, gs);
    cvt_all_kernel<<<(unsigned)((CVT_TOT + 255) / 256), 256>>>(
        x, w_qkv, w_proj, xh, wq, wp);

    // 2) QKV projection + fused RoPE (64x128 tiles, 3 CTAs/SM)
    cudaFuncSetAttribute(gemm_qkv_rope_kernel,
                         cudaFuncAttributeMaxDynamicSharedMemorySize, QKV_SMEM);
    gemm_qkv_rope_kernel<<<dim3(QKV_N / 128, MROWS / 64), 128, QKV_SMEM>>>(
        xh, wq, gc, gs, qh, kh, vh);

    // 3) flash attention (FBQ=64) -> y fp16
    cudaFuncSetAttribute(flash_mma_kernel,
                         cudaFuncAttributeMaxDynamicSharedMemorySize, FA2_SMEM);
    flash_mma_kernel<<<dim3(SEQ / FBQ, BHN), 128, FA2_SMEM>>>(
        qh, kh, vh, yh);

    // 4) output projection (plain fp16 HMMA, fp32 out)
    cudaFuncSetAttribute(gemm_fp16_kernel,
                         cudaFuncAttributeMaxDynamicSharedMemorySize, GEMM_SMEM);
    gemm_fp16_kernel<<<dim3(NEMBD / 128, MROWS / 128), 256, GEMM_SMEM>>>(
        yh, wp, out, MROWS, NEMBD, NEMBD);
}

// round 16
// speedup vs baseline: 1.5144x; 1.5144x over previous
#include <cuda_runtime.h>
#include <cuda_fp16.h>
#include <math.h>
#include <stdint.h>

// ---------------- problem constants ----------------
#define NEMBD   2048
#define NH      16
#define DH      128
#define BATCH   2
#define SEQ     2048
#define MROWS   (BATCH*SEQ)     // 4096
#define QKV_N   (3*NEMBD)       // 6144
#define BHN     (BATCH*NH)      // 32

// ---------------- scratch (device globals, no runtime allocs) ----------------
__device__ __half g_qh[(size_t)BHN*SEQ*DH];
__device__ __half g_kh[(size_t)BHN*SEQ*DH];
__device__ __half g_vh[(size_t)BHN*SEQ*DH];
__device__ __half g_xh[(size_t)MROWS*NEMBD];
__device__ __half g_wq[(size_t)QKV_N*NEMBD];
__device__ __half g_wp[(size_t)NEMBD*NEMBD];
__device__ __half g_yh[(size_t)MROWS*NEMBD];
__device__ float g_cos[SEQ*64];
__device__ float g_sin[SEQ*64];

// ================= common asm helpers =================
#define MMA16816(d, a0, a1, a2, a3, b0, b1)                                \
    asm volatile(                                                          \
        "mma.sync.aligned.m16n8k16.row.col.f32.f16.f16.f32 "               \
        "{%0,%1,%2,%3}, {%4,%5,%6,%7}, {%8,%9}, {%0,%1,%2,%3};"            \
        : "+f"((d)[0]), "+f"((d)[1]), "+f"((d)[2]), "+f"((d)[3])           \
        : "r"(a0), "r"(a1), "r"(a2), "r"(a3), "r"(b0), "r"(b1))

#define LDSM_X4(r0, r1, r2, r3, addr)                                       \
    asm volatile("ldmatrix.sync.aligned.m8n8.x4.shared.b16 "                \
                 "{%0,%1,%2,%3}, [%4];"                                     \
                 : "=r"(r0), "=r"(r1), "=r"(r2), "=r"(r3) : "r"(addr))

#define LDSM_X4T(r0, r1, r2, r3, addr)                                      \
    asm volatile("ldmatrix.sync.aligned.m8n8.x4.trans.shared.b16 "          \
                 "{%0,%1,%2,%3}, [%4];"                                     \
                 : "=r"(r0), "=r"(r1), "=r"(r2), "=r"(r3) : "r"(addr))

#define CP_ASYNC16(dst, src)                                                \
    asm volatile("cp.async.cg.shared.global [%0], [%1], 16;"                \
                 :: "r"(dst), "l"(src))
#define CP_COMMIT() asm volatile("cp.async.commit_group;" ::: "memory")
#define CP_WAIT1()  asm volatile("cp.async.wait_group 1;" ::: "memory")
#define CP_WAIT0()  asm volatile("cp.async.wait_group 0;" ::: "memory")

__device__ __forceinline__ uint32_t smem_u32(const void* p) {
    uint32_t a;
    asm("{ .reg .u64 t; cvta.to.shared.u64 t, %1; cvt.u32.u64 %0, t; }"
        : "=r"(a) : "l"(p));
    return a;
}

__device__ __forceinline__ uint32_t fp16_pack2(float x, float y) {
    __half2 h = __floats2half2_rn(x, y);
    return *(uint32_t*)&h;
}

// ================= RoPE tables (fp64 angles) =================
__global__ void rope_table_kernel(float* gcos, float* gsin) {
    int idx = blockIdx.x * blockDim.x + threadIdx.x;
    if (idx >= SEQ * 64) return;
    int t = idx >> 6;
    int i = idx & 63;
    double freq = exp(-((double)(2 * i) / 128.0) * log(10000.0));
    double ang = (double)t * freq;
    gcos[idx] = (float)cos(ang);
    gsin[idx] = (float)sin(ang);
}

// ============ fused fp32 -> fp16 convert for x, w_qkv, w_proj ================
#define CVT_N1 ((long long)MROWS * NEMBD / 4)
#define CVT_N2 ((long long)QKV_N * NEMBD / 4)
#define CVT_N3 ((long long)NEMBD * NEMBD / 4)
#define CVT_TOT (CVT_N1 + CVT_N2 + CVT_N3)

__global__ void cvt_all_kernel(const float* __restrict__ x,
                               const float* __restrict__ wq32,
                               const float* __restrict__ wp32,
                               __half* __restrict__ xh,
                               __half* __restrict__ wq,
                               __half* __restrict__ wp) {
    long long i = (long long)blockIdx.x * blockDim.x + threadIdx.x;
    if (i >= CVT_TOT) return;
    const float* src;
    __half* dst;
    long long j;
    if (i < CVT_N1)               { src = x;    dst = xh; j = i; }
    else if (i < CVT_N1 + CVT_N2) { src = wq32; dst = wq; j = i - CVT_N1; }
    else                          { src = wp32; dst = wp; j = i - CVT_N1 - CVT_N2; }
    float4 v = *(const float4*)(src + j * 4);
    *(uint2*)(dst + j * 4) = make_uint2(fp16_pack2(v.x, v.y), fp16_pack2(v.z, v.w));
}

// ================= shared GEMM tiling constants =================
#define SLD 40
#define GARR 10240
#define GSTG (2*GARR)
#define GEMM_SMEM (2*GSTG)
#define RLD 132

// ===== QKV GEMM with fused RoPE epilogue (R11/R13/R14-proven) ================
__global__ __launch_bounds__(256, 2)
void gemm_qkv_rope_kernel(const __half* __restrict__ A,
                          const __half* __restrict__ W,
                          const float* __restrict__ gcos,
                          const float* __restrict__ gsin,
                          __half* __restrict__ qh,
                          __half* __restrict__ kh,
                          __half* __restrict__ vh) {
    extern __shared__ char gsm[];
    const uint32_t sb = smem_u32(gsm);
    const int K = NEMBD;

    const int tid  = threadIdx.x;
    const int warp = tid >> 5, lane = tid & 31;
    const int g = lane >> 2, t = lane & 3;
    const int wm = warp & 3, wn = warp >> 2;
    const int m0 = blockIdx.y * 128;
    const int n0 = blockIdx.x * 128;
    const int NT = K / 32;

    float acc[2][8][4];
#pragma unroll
    for (int mf = 0; mf < 2; mf++)
#pragma unroll
        for (int nf = 0; nf < 8; nf++)
#pragma unroll
            for (int r = 0; r < 4; r++) acc[mf][nf][r] = 0.0f;

    auto prefetch = [&](int s, int kt) {
#pragma unroll
        for (int it = 0; it < 4; it++) {
            int i = tid + it * 256;
            int arr = i >> 9;
            int row = (i >> 2) & 127;
            int ch  = i & 3;
            const __half* src =
                (arr == 0) ? A + (size_t)(m0 + row) * K :
                             W + (size_t)(n0 + row) * K;
            src += kt * 32 + ch * 8;
            uint32_t dst = sb + (uint32_t)(s * GSTG + arr * GARR + row * 80 + ch * 16);
            CP_ASYNC16(dst, src);
        }
    };

    prefetch(0, 0);
    CP_COMMIT();

    for (int kt = 0; kt < NT; kt++) {
        if (kt + 1 < NT) {
            prefetch((kt + 1) & 1, kt + 1);
            CP_COMMIT();
            CP_WAIT1();
        } else {
            CP_WAIT0();
        }
        __syncthreads();

        const __half* As = (const __half*)(gsm + (size_t)(kt & 1) * GSTG);
        const __half* Ws = As + GARR / 2;

#pragma unroll
        for (int kk = 0; kk < 32; kk += 16) {
            uint32_t a[2][4];
#pragma unroll
            for (int mf = 0; mf < 2; mf++) {
                int r = wm * 32 + mf * 16 + g;
                const __half* p = &As[r * SLD + kk + 2 * t];
                a[mf][0] = *(const uint32_t*)p;
                a[mf][1] = *(const uint32_t*)(p + 8 * SLD);
                a[mf][2] = *(const uint32_t*)(p + 8);
                a[mf][3] = *(const uint32_t*)(p + 8 * SLD + 8);
            }
#pragma unroll
            for (int nf = 0; nf < 8; nf++) {
                const __half* p = &Ws[(wn * 64 + nf * 8 + g) * SLD + kk + 2 * t];
                uint32_t w0 = *(const uint32_t*)p;
                uint32_t w1 = *(const uint32_t*)(p + 8);
#pragma unroll
                for (int mf = 0; mf < 2; mf++)
                    MMA16816(acc[mf][nf], a[mf][0], a[mf][1], a[mf][2], a[mf][3], w0, w1);
            }
        }
        __syncthreads();
    }

    const int part = n0 >> 11;
    const int h    = (n0 & 2047) >> 7;

    if (part == 2) {
#pragma unroll
        for (int mf = 0; mf < 2; mf++) {
            int m = m0 + wm * 32 + mf * 16 + g;
            int b0 = m >> 11, t0 = m & 2047;
            int b1 = (m + 8) >> 11, t1 = (m + 8) & 2047;
            size_t o0 = ((size_t)(b0 * 16 + h) * SEQ + t0) * DH;
            size_t o1 = ((size_t)(b1 * 16 + h) * SEQ + t1) * DH;
#pragma unroll
            for (int nf = 0; nf < 8; nf++) {
                int d = wn * 64 + nf * 8 + 2 * t;
                *(uint32_t*)(vh + o0 + d) = fp16_pack2(acc[mf][nf][0], acc[mf][nf][1]);
                *(uint32_t*)(vh + o1 + d) = fp16_pack2(acc[mf][nf][2], acc[mf][nf][3]);
            }
        }
    } else {
        float* stage = (float*)gsm;
        const float qscale = 0.08838834764831845f;
#pragma unroll
        for (int half = 0; half < 2; half++) {
            __syncthreads();
            if ((wm >> 1) == half) {
                int baserow = wm * 32 - half * 64;
#pragma unroll
                for (int mf = 0; mf < 2; mf++) {
                    int lr0 = baserow + mf * 16 + g;
#pragma unroll
                    for (int nf = 0; nf < 8; nf++) {
                        int col = wn * 64 + nf * 8 + 2 * t;
                        stage[lr0 * RLD + col]           = acc[mf][nf][0];
                        stage[lr0 * RLD + col + 1]       = acc[mf][nf][1];
                        stage[(lr0 + 8) * RLD + col]     = acc[mf][nf][2];
                        stage[(lr0 + 8) * RLD + col + 1] = acc[mf][nf][3];
                    }
                }
            }
            __syncthreads();
#pragma unroll
            for (int it = 0; it < 32; it++) {
                int idx = tid + it * 256;
                int lr = idx >> 7, d = idx & 127;
                int m = m0 + half * 64 + lr;
                int trow = m & 2047, b = m >> 11;
                float val = stage[lr * RLD + d];
                float par = stage[lr * RLD + (d ^ 64)];
                int ci = d & 63;
                float c  = gcos[trow * 64 + ci];
                float sn = gsin[trow * 64 + ci];
                float rot = (d < 64) ? -par : par;
                float outv = val * c + rot * sn;
                size_t o = ((size_t)(b * 16 + h) * SEQ + trow) * DH + d;
                if (part == 0) qh[o] = __float2half_rn(outv * qscale);
                else           kh[o] = __float2half_rn(outv);
            }
        }
    }
}

// ===== plain fp16 HMMA GEMM (output projection) ==============================
__global__ __launch_bounds__(256, 2)
void gemm_fp16_kernel(const __half* __restrict__ A,
                      const __half* __restrict__ W,
                      float* __restrict__ C, int M, int N, int K) {
    extern __shared__ char gsm[];
    const uint32_t sb = smem_u32(gsm);

    const int tid  = threadIdx.x;
    const int warp = tid >> 5, lane = tid & 31;
    const int g = lane >> 2, t = lane & 3;
    const int wm = warp & 3, wn = warp >> 2;
    const int m0 = blockIdx.y * 128;
    const int n0 = blockIdx.x * 128;
    const int NT = K / 32;

    float acc[2][8][4];
#pragma unroll
    for (int mf = 0; mf < 2; mf++)
#pragma unroll
        for (int nf = 0; nf < 8; nf++)
#pragma unroll
            for (int r = 0; r < 4; r++) acc[mf][nf][r] = 0.0f;

    auto prefetch = [&](int s, int kt) {
#pragma unroll
        for (int it = 0; it < 4; it++) {
            int i = tid + it * 256;
            int arr = i >> 9;
            int row = (i >> 2) & 127;
            int ch  = i & 3;
            const __half* src =
                (arr == 0) ? A + (size_t)(m0 + row) * K :
                             W + (size_t)(n0 + row) * K;
            src += kt * 32 + ch * 8;
            uint32_t dst = sb + (uint32_t)(s * GSTG + arr * GARR + row * 80 + ch * 16);
            CP_ASYNC16(dst, src);
        }
    };

    prefetch(0, 0);
    CP_COMMIT();

    for (int kt = 0; kt < NT; kt++) {
        if (kt + 1 < NT) {
            prefetch((kt + 1) & 1, kt + 1);
            CP_COMMIT();
            CP_WAIT1();
        } else {
            CP_WAIT0();
        }
        __syncthreads();

        const __half* As = (const __half*)(gsm + (size_t)(kt & 1) * GSTG);
        const __half* Ws = As + GARR / 2;

#pragma unroll
        for (int kk = 0; kk < 32; kk += 16) {
            uint32_t a[2][4];
#pragma unroll
            for (int mf = 0; mf < 2; mf++) {
                int r = wm * 32 + mf * 16 + g;
                const __half* p = &As[r * SLD + kk + 2 * t];
                a[mf][0] = *(const uint32_t*)p;
                a[mf][1] = *(const uint32_t*)(p + 8 * SLD);
                a[mf][2] = *(const uint32_t*)(p + 8);
                a[mf][3] = *(const uint32_t*)(p + 8 * SLD + 8);
            }
#pragma unroll
            for (int nf = 0; nf < 8; nf++) {
                const __half* p = &Ws[(wn * 64 + nf * 8 + g) * SLD + kk + 2 * t];
                uint32_t w0 = *(const uint32_t*)p;
                uint32_t w1 = *(const uint32_t*)(p + 8);
#pragma unroll
                for (int mf = 0; mf < 2; mf++)
                    MMA16816(acc[mf][nf], a[mf][0], a[mf][1], a[mf][2], a[mf][3], w0, w1);
            }
        }
        __syncthreads();
    }

#pragma unroll
    for (int mf = 0; mf < 2; mf++) {
        int r0 = m0 + wm * 32 + mf * 16 + g;
#pragma unroll
        for (int nf = 0; nf < 8; nf++) {
            int col = n0 + wn * 64 + nf * 8 + 2 * t;
            float* p0 = C + (size_t)r0 * N + col;
            float* p1 = C + (size_t)(r0 + 8) * N + col;
            *(float2*)p0 = make_float2(acc[mf][nf][0], acc[mf][nf][1]);
            *(float2*)p1 = make_float2(acc[mf][nf][2], acc[mf][nf][3]);
        }
    }
}

// ============ flash attention: FBQ=64, 128 threads, 2 CTAs/SM ================
#define FBQ 64
#define FBK 64
#define FLD 136
#define ARRB 17408u                 // 64 rows * 272 B
#define STG_B (2 * 17408)           // K, V
#define FA2_SMEM (2 * STG_B)        // 69632 B per CTA

__global__ __launch_bounds__(128, 2)
void flash_mma_kernel(const __half* __restrict__ Qg,
                      const __half* __restrict__ KH,
                      const __half* __restrict__ VH,
                      __half* __restrict__ Yh) {
    extern __shared__ char smc[];
    const uint32_t sbase = smem_u32(smc);

    const int tid  = threadIdx.x;
    const int w    = tid >> 5, lane = tid & 31;   // w in 0..3
    const int g    = lane >> 2, t = lane & 3;
    const int qi   = gridDim.x - 1 - blockIdx.x;
    const int bh   = blockIdx.y;
    const int qbase = qi * FBQ;

    const size_t bhoff = (size_t)bh * SEQ * DH;

    uint32_t qf[8][4];
    {
        const __half* q0 = Qg + bhoff + (size_t)(qbase + w * 16 + g) * DH;
        const __half* q1 = q0 + 8 * DH;
#pragma unroll
        for (int kf = 0; kf < 8; kf++) {
            qf[kf][0] = *(const uint32_t*)(q0 + 16 * kf + 2 * t);
            qf[kf][1] = *(const uint32_t*)(q1 + 16 * kf + 2 * t);
            qf[kf][2] = *(const uint32_t*)(q0 + 16 * kf + 2 * t + 8);
            qf[kf][3] = *(const uint32_t*)(q1 + 16 * kf + 2 * t + 8);
        }
    }

    const uint32_t lmK = (uint32_t)(((lane & 7) * FLD + (lane >> 3) * 8) * 2);
    const uint32_t lmV = (uint32_t)((((lane & 7) + ((lane >> 3) & 1) * 8) * FLD
                                     + (lane >> 4) * 8) * 2);

    float m0r = -1e30f, m1r = -1e30f, l0r = 0.0f, l1r = 0.0f;
    float o[16][4];
#pragma unroll
    for (int nf = 0; nf < 16; nf++)
#pragma unroll
        for (int r = 0; r < 4; r++) o[nf][r] = 0.0f;

    const int nkt = qi + 1;

    auto prefetch = [&](int s, int kt) {
        const int kb = kt * FBK;
        const __half* srcs[2] = { KH + bhoff + (size_t)kb * DH,
                                  VH + bhoff + (size_t)kb * DH };
        uint32_t dst0 = sbase + (uint32_t)s * STG_B;
#pragma unroll
        for (int it = 0; it < 16; it++) {
            int i = tid + it * 128;
            int arr = i >> 10, key = (i >> 4) & 63, ch = i & 15;
            const __half* src = srcs[arr] + key * DH + ch * 8;
            uint32_t dst = dst0 + (uint32_t)(arr * ARRB + key * 272 + ch * 16);
            CP_ASYNC16(dst, src);
        }
    };

    prefetch(0, 0);
    CP_COMMIT();

    for (int kt = 0; kt < nkt; kt++) {
        if (kt + 1 < nkt) {
            prefetch((kt + 1) & 1, kt + 1);
            CP_COMMIT();
            CP_WAIT1();
        } else {
            CP_WAIT0();
        }
        __syncthreads();

        const int kbase = kt * FBK;
        {
            const uint32_t stg = sbase + (uint32_t)(kt & 1) * STG_B;

            float s[8][4];
#pragma unroll
            for (int nf = 0; nf < 8; nf++)
#pragma unroll
                for (int r = 0; r < 4; r++) s[nf][r] = 0.0f;

#pragma unroll
            for (int kf2 = 0; kf2 < 4; kf2++) {
#pragma unroll
                for (int nf = 0; nf < 8; nf++) {
                    uint32_t off = (uint32_t)((nf * 8 * FLD + kf2 * 32) * 2);
                    uint32_t k0, k1, k2, k3;
                    LDSM_X4(k0, k1, k2, k3, stg + lmK + off);
                    MMA16816(s[nf], qf[2*kf2][0], qf[2*kf2][1], qf[2*kf2][2], qf[2*kf2][3], k0, k1);
                    MMA16816(s[nf], qf[2*kf2+1][0], qf[2*kf2+1][1], qf[2*kf2+1][2], qf[2*kf2+1][3], k2, k3);
                }
            }

            const int row0 = qbase + w * 16 + g;
            const int row1 = row0 + 8;
            if (kbase + FBK - 1 > qbase + w * 16) {
#pragma unroll
                for (int nf = 0; nf < 8; nf++) {
                    int c0 = kbase + 8 * nf + 2 * t;
                    if (c0 > row0)     s[nf][0] = -1e30f;
                    if (c0 + 1 > row0) s[nf][1] = -1e30f;
                    if (c0 > row1)     s[nf][2] = -1e30f;
                    if (c0 + 1 > row1) s[nf][3] = -1e30f;
                }
            }

            float mx0 = -1e30f, mx1 = -1e30f;
#pragma unroll
            for (int nf = 0; nf < 8; nf++) {
                mx0 = fmaxf(mx0, fmaxf(s[nf][0], s[nf][1]));
                mx1 = fmaxf(mx1, fmaxf(s[nf][2], s[nf][3]));
            }
            mx0 = fmaxf(mx0, __shfl_xor_sync(0xffffffffu, mx0, 1));
            mx0 = fmaxf(mx0, __shfl_xor_sync(0xffffffffu, mx0, 2));
            mx1 = fmaxf(mx1, __shfl_xor_sync(0xffffffffu, mx1, 1));
            mx1 = fmaxf(mx1, __shfl_xor_sync(0xffffffffu, mx1, 2));
            float mn0 = fmaxf(m0r, mx0), mn1 = fmaxf(m1r, mx1);
            float a0 = __expf(m0r - mn0), a1 = __expf(m1r - mn1);
            m0r = mn0; m1r = mn1;
            float rs0 = 0.0f, rs1 = 0.0f;
#pragma unroll
            for (int nf = 0; nf < 8; nf++) {
                s[nf][0] = __expf(s[nf][0] - mn0);
                s[nf][1] = __expf(s[nf][1] - mn0);
                s[nf][2] = __expf(s[nf][2] - mn1);
                s[nf][3] = __expf(s[nf][3] - mn1);
                rs0 += s[nf][0] + s[nf][1];
                rs1 += s[nf][2] + s[nf][3];
            }
            rs0 += __shfl_xor_sync(0xffffffffu, rs0, 1);
            rs0 += __shfl_xor_sync(0xffffffffu, rs0, 2);
            rs1 += __shfl_xor_sync(0xffffffffu, rs1, 1);
            rs1 += __shfl_xor_sync(0xffffffffu, rs1, 2);
            l0r = l0r * a0 + rs0;
            l1r = l1r * a1 + rs1;
#pragma unroll
            for (int nf = 0; nf < 16; nf++) {
                o[nf][0] *= a0; o[nf][1] *= a0;
                o[nf][2] *= a1; o[nf][3] *= a1;
            }

#pragma unroll
            for (int kf = 0; kf < 4; kf++) {
                uint32_t ph[4];
                ph[0] = fp16_pack2(s[2*kf][0],   s[2*kf][1]);
                ph[1] = fp16_pack2(s[2*kf][2],   s[2*kf][3]);
                ph[2] = fp16_pack2(s[2*kf+1][0], s[2*kf+1][1]);
                ph[3] = fp16_pack2(s[2*kf+1][2], s[2*kf+1][3]);
                uint32_t voff = (uint32_t)((kf * 16 * FLD) * 2);
#pragma unroll
                for (int nf2 = 0; nf2 < 8; nf2++) {
                    uint32_t off = voff + (uint32_t)(nf2 * 32);
                    uint32_t v0, v1, v2, v3;
                    LDSM_X4T(v0, v1, v2, v3, stg + ARRB + lmV + off);
                    MMA16816(o[2*nf2],   ph[0], ph[1], ph[2], ph[3], v0, v1);
                    MMA16816(o[2*nf2+1], ph[0], ph[1], ph[2], ph[3], v2, v3);
                }
            }
        }
        __syncthreads();
    }

    const int b = bh >> 4, h = bh & 15;
    const int row0 = qbase + w * 16 + g;
    const float inv0 = 1.0f / l0r, inv1 = 1.0f / l1r;
    size_t y0off = ((size_t)(b * SEQ + row0)) * NEMBD + h * DH;
    size_t y1off = ((size_t)(b * SEQ + row0 + 8)) * NEMBD + h * DH;
#pragma unroll
    for (int nf = 0; nf < 16; nf++) {
        int col = 8 * nf + 2 * t;
        *(uint32_t*)(Yh + y0off + col) = fp16_pack2(o[nf][0] * inv0, o[nf][1] * inv0);
        *(uint32_t*)(Yh + y1off + col) = fp16_pack2(o[nf][2] * inv1, o[nf][3] * inv1);
    }
}

// ================= launch =====================================================
extern "C" void kernel_launch(void* const* d_in, const int* in_sizes, int n_in,
                              void* d_out, int out_size) {
    const float* x      = (const float*)d_in[0];
    const float* w_qkv  = (const float*)d_in[1];
    const float* w_proj = (const float*)d_in[2];
    float* out = (float*)d_out;

    float *gc, *gs;
    __half *qh, *kh, *vh, *xh, *wq, *wp, *yh;
    cudaGetSymbolAddress((void**)&qh, g_qh);
    cudaGetSymbolAddress((void**)&kh, g_kh);
    cudaGetSymbolAddress((void**)&vh, g_vh);
    cudaGetSymbolAddress((void**)&xh, g_xh);
    cudaGetSymbolAddress((void**)&wq, g_wq);
    cudaGetSymbolAddress((void**)&wp, g_wp);
    cudaGetSymbolAddress((void**)&yh, g_yh);
    cudaGetSymbolAddress((void**)&gc, g_cos);
    cudaGetSymbolAddress((void**)&gs, g_sin);

    // 1) RoPE tables + fused operand conversions
    rope_table_kernel<<<(SEQ * 64 + 255) / 256, 256>>>(gc, gs);
    cvt_all_kernel<<<(unsigned)((CVT_TOT + 255) / 256), 256>>>(
        x, w_qkv, w_proj, xh, wq, wp);

    // 2) QKV projection + fused RoPE -> qh(scaled)/kh/vh fp16
    cudaFuncSetAttribute(gemm_qkv_rope_kernel,
                         cudaFuncAttributeMaxDynamicSharedMemorySize, GEMM_SMEM);
    gemm_qkv_rope_kernel<<<dim3(QKV_N / 128, MROWS / 128), 256, GEMM_SMEM>>>(
        xh, wq, gc, gs, qh, kh, vh);

    // 3) flash attention (FBQ=64, 2 CTAs/SM) -> y fp16
    cudaFuncSetAttribute(flash_mma_kernel,
                         cudaFuncAttributeMaxDynamicSharedMemorySize, FA2_SMEM);
    flash_mma_kernel<<<dim3(SEQ / FBQ, BHN), 128, FA2_SMEM>>>(
        qh, kh, vh, yh);

    // 4) output projection (plain fp16 HMMA, fp32 out)
    cudaFuncSetAttribute(gemm_fp16_kernel,
                         cudaFuncAttributeMaxDynamicSharedMemorySize, GEMM_SMEM);
    gemm_fp16_kernel<<<dim3(NEMBD / 128, MROWS / 128), 256, GEMM_SMEM>>>(
        yh, wp, out, MROWS, NEMBD, NEMBD);
}

// round 17
// speedup vs baseline: 1.6473x; 1.0877x over previous
#include <cuda_runtime.h>
#include <cuda_fp16.h>
#include <math.h>
#include <stdint.h>

// ---------------- problem constants ----------------
#define NEMBD   2048
#define NH      16
#define DH      128
#define BATCH   2
#define SEQ     2048
#define MROWS   (BATCH*SEQ)     // 4096
#define QKV_N   (3*NEMBD)       // 6144
#define BHN     (BATCH*NH)      // 32

// ---------------- scratch (device globals, no runtime allocs) ----------------
__device__ __half g_qh[(size_t)BHN*SEQ*DH];
__device__ __half g_kh[(size_t)BHN*SEQ*DH];
__device__ __half g_vh[(size_t)BHN*SEQ*DH];
__device__ __half g_xh[(size_t)MROWS*NEMBD];
__device__ __half g_wq[(size_t)QKV_N*NEMBD];
__device__ __half g_wp[(size_t)NEMBD*NEMBD];
__device__ __half g_yh[(size_t)MROWS*NEMBD];
__device__ float g_cos[SEQ*64];
__device__ float g_sin[SEQ*64];

// ================= common asm helpers =================
#define MMA16816(d, a0, a1, a2, a3, b0, b1)                                \
    asm volatile(                                                          \
        "mma.sync.aligned.m16n8k16.row.col.f32.f16.f16.f32 "               \
        "{%0,%1,%2,%3}, {%4,%5,%6,%7}, {%8,%9}, {%0,%1,%2,%3};"            \
        : "+f"((d)[0]), "+f"((d)[1]), "+f"((d)[2]), "+f"((d)[3])           \
        : "r"(a0), "r"(a1), "r"(a2), "r"(a3), "r"(b0), "r"(b1))

#define LDSM_X4(r0, r1, r2, r3, addr)                                       \
    asm volatile("ldmatrix.sync.aligned.m8n8.x4.shared.b16 "                \
                 "{%0,%1,%2,%3}, [%4];"                                     \
                 : "=r"(r0), "=r"(r1), "=r"(r2), "=r"(r3) : "r"(addr))

#define LDSM_X4T(r0, r1, r2, r3, addr)                                      \
    asm volatile("ldmatrix.sync.aligned.m8n8.x4.trans.shared.b16 "          \
                 "{%0,%1,%2,%3}, [%4];"                                     \
                 : "=r"(r0), "=r"(r1), "=r"(r2), "=r"(r3) : "r"(addr))

#define CP_ASYNC16(dst, src)                                                \
    asm volatile("cp.async.cg.shared.global [%0], [%1], 16;"                \
                 :: "r"(dst), "l"(src))
#define CP_COMMIT() asm volatile("cp.async.commit_group;" ::: "memory")
#define CP_WAIT1()  asm volatile("cp.async.wait_group 1;" ::: "memory")
#define CP_WAIT0()  asm volatile("cp.async.wait_group 0;" ::: "memory")

__device__ __forceinline__ uint32_t smem_u32(const void* p) {
    uint32_t a;
    asm("{ .reg .u64 t; cvta.to.shared.u64 t, %1; cvt.u32.u64 %0, t; }"
        : "=r"(a) : "l"(p));
    return a;
}

__device__ __forceinline__ uint32_t fp16_pack2(float x, float y) {
    __half2 h = __floats2half2_rn(x, y);
    return *(uint32_t*)&h;
}

// ================= RoPE tables (fp64 angles) =================
__global__ void rope_table_kernel(float* gcos, float* gsin) {
    int idx = blockIdx.x * blockDim.x + threadIdx.x;
    if (idx >= SEQ * 64) return;
    int t = idx >> 6;
    int i = idx & 63;
    double freq = exp(-((double)(2 * i) / 128.0) * log(10000.0));
    double ang = (double)t * freq;
    gcos[idx] = (float)cos(ang);
    gsin[idx] = (float)sin(ang);
}

// ============ fused fp32 -> fp16 convert for x, w_qkv, w_proj ================
#define CVT_N1 ((long long)MROWS * NEMBD / 4)
#define CVT_N2 ((long long)QKV_N * NEMBD / 4)
#define CVT_N3 ((long long)NEMBD * NEMBD / 4)
#define CVT_TOT (CVT_N1 + CVT_N2 + CVT_N3)

__global__ void cvt_all_kernel(const float* __restrict__ x,
                               const float* __restrict__ wq32,
                               const float* __restrict__ wp32,
                               __half* __restrict__ xh,
                               __half* __restrict__ wq,
                               __half* __restrict__ wp) {
    long long i = (long long)blockIdx.x * blockDim.x + threadIdx.x;
    if (i >= CVT_TOT) return;
    const float* src;
    __half* dst;
    long long j;
    if (i < CVT_N1)               { src = x;    dst = xh; j = i; }
    else if (i < CVT_N1 + CVT_N2) { src = wq32; dst = wq; j = i - CVT_N1; }
    else                          { src = wp32; dst = wp; j = i - CVT_N1 - CVT_N2; }
    float4 v = *(const float4*)(src + j * 4);
    *(uint2*)(dst + j * 4) = make_uint2(fp16_pack2(v.x, v.y), fp16_pack2(v.z, v.w));
}

// ================= shared GEMM tiling constants =================
#define SLD 40
#define GARR 10240
#define GSTG (2*GARR)               // A, W = 20480 B per stage
#define GEMM_SMEM (3*GSTG)          // 3-stage pipeline = 61440 B
#define RLD 132

// ===== QKV GEMM with fused RoPE epilogue (3-stage, 1 sync/iter) ==============
__global__ __launch_bounds__(256, 2)
void gemm_qkv_rope_kernel(const __half* __restrict__ A,
                          const __half* __restrict__ W,
                          const float* __restrict__ gcos,
                          const float* __restrict__ gsin,
                          __half* __restrict__ qh,
                          __half* __restrict__ kh,
                          __half* __restrict__ vh) {
    extern __shared__ char gsm[];
    const uint32_t sb = smem_u32(gsm);
    const int K = NEMBD;

    const int tid  = threadIdx.x;
    const int warp = tid >> 5, lane = tid & 31;
    const int g = lane >> 2, t = lane & 3;
    const int wm = warp & 3, wn = warp >> 2;
    const int m0 = blockIdx.y * 128;
    const int n0 = blockIdx.x * 128;
    const int NT = K / 32;

    float acc[2][8][4];
#pragma unroll
    for (int mf = 0; mf < 2; mf++)
#pragma unroll
        for (int nf = 0; nf < 8; nf++)
#pragma unroll
            for (int r = 0; r < 4; r++) acc[mf][nf][r] = 0.0f;

    auto prefetch = [&](int s, int kt) {
#pragma unroll
        for (int it = 0; it < 4; it++) {
            int i = tid + it * 256;
            int arr = i >> 9;
            int row = (i >> 2) & 127;
            int ch  = i & 3;
            const __half* src =
                (arr == 0) ? A + (size_t)(m0 + row) * K :
                             W + (size_t)(n0 + row) * K;
            src += kt * 32 + ch * 8;
            uint32_t dst = sb + (uint32_t)(s * GSTG + arr * GARR + row * 80 + ch * 16);
            CP_ASYNC16(dst, src);
        }
    };

    prefetch(0, 0);
    CP_COMMIT();
    prefetch(1, 1);
    CP_COMMIT();

    for (int kt = 0; kt < NT; kt++) {
        if (kt + 1 < NT) CP_WAIT1(); else CP_WAIT0();
        __syncthreads();   // stage kt%3 ready; stage (kt+2)%3 reads (iter kt-1) done

        const int st = kt - (kt / 3) * 3;
        const __half* As = (const __half*)(gsm + (size_t)st * GSTG);
        const __half* Ws = As + GARR / 2;

#pragma unroll
        for (int kk = 0; kk < 32; kk += 16) {
            uint32_t a[2][4];
#pragma unroll
            for (int mf = 0; mf < 2; mf++) {
                int r = wm * 32 + mf * 16 + g;
                const __half* p = &As[r * SLD + kk + 2 * t];
                a[mf][0] = *(const uint32_t*)p;
                a[mf][1] = *(const uint32_t*)(p + 8 * SLD);
                a[mf][2] = *(const uint32_t*)(p + 8);
                a[mf][3] = *(const uint32_t*)(p + 8 * SLD + 8);
            }
#pragma unroll
            for (int nf = 0; nf < 8; nf++) {
                const __half* p = &Ws[(wn * 64 + nf * 8 + g) * SLD + kk + 2 * t];
                uint32_t w0 = *(const uint32_t*)p;
                uint32_t w1 = *(const uint32_t*)(p + 8);
#pragma unroll
                for (int mf = 0; mf < 2; mf++)
                    MMA16816(acc[mf][nf], a[mf][0], a[mf][1], a[mf][2], a[mf][3], w0, w1);
            }
        }

        if (kt + 2 < NT) {
            int s2 = (kt + 2) - ((kt + 2) / 3) * 3;
            prefetch(s2, kt + 2);
            CP_COMMIT();
        }
    }

    const int part = n0 >> 11;
    const int h    = (n0 & 2047) >> 7;

    if (part == 2) {
#pragma unroll
        for (int mf = 0; mf < 2; mf++) {
            int m = m0 + wm * 32 + mf * 16 + g;
            int b0 = m >> 11, t0 = m & 2047;
            int b1 = (m + 8) >> 11, t1 = (m + 8) & 2047;
            size_t o0 = ((size_t)(b0 * 16 + h) * SEQ + t0) * DH;
            size_t o1 = ((size_t)(b1 * 16 + h) * SEQ + t1) * DH;
#pragma unroll
            for (int nf = 0; nf < 8; nf++) {
                int d = wn * 64 + nf * 8 + 2 * t;
                *(uint32_t*)(vh + o0 + d) = fp16_pack2(acc[mf][nf][0], acc[mf][nf][1]);
                *(uint32_t*)(vh + o1 + d) = fp16_pack2(acc[mf][nf][2], acc[mf][nf][3]);
            }
        }
    } else {
        float* stage = (float*)gsm;
        const float qscale = 0.08838834764831845f;
#pragma unroll
        for (int half = 0; half < 2; half++) {
            __syncthreads();
            if ((wm >> 1) == half) {
                int baserow = wm * 32 - half * 64;
#pragma unroll
                for (int mf = 0; mf < 2; mf++) {
                    int lr0 = baserow + mf * 16 + g;
#pragma unroll
                    for (int nf = 0; nf < 8; nf++) {
                        int col = wn * 64 + nf * 8 + 2 * t;
                        stage[lr0 * RLD + col]           = acc[mf][nf][0];
                        stage[lr0 * RLD + col + 1]       = acc[mf][nf][1];
                        stage[(lr0 + 8) * RLD + col]     = acc[mf][nf][2];
                        stage[(lr0 + 8) * RLD + col + 1] = acc[mf][nf][3];
                    }
                }
            }
            __syncthreads();
#pragma unroll
            for (int it = 0; it < 32; it++) {
                int idx = tid + it * 256;
                int lr = idx >> 7, d = idx & 127;
                int m = m0 + half * 64 + lr;
                int trow = m & 2047, b = m >> 11;
                float val = stage[lr * RLD + d];
                float par = stage[lr * RLD + (d ^ 64)];
                int ci = d & 63;
                float c  = gcos[trow * 64 + ci];
                float sn = gsin[trow * 64 + ci];
                float rot = (d < 64) ? -par : par;
                float outv = val * c + rot * sn;
                size_t o = ((size_t)(b * 16 + h) * SEQ + trow) * DH + d;
                if (part == 0) qh[o] = __float2half_rn(outv * qscale);
                else           kh[o] = __float2half_rn(outv);
            }
        }
    }
}

// ===== plain fp16 HMMA GEMM (output projection, 3-stage) =====================
__global__ __launch_bounds__(256, 2)
void gemm_fp16_kernel(const __half* __restrict__ A,
                      const __half* __restrict__ W,
                      float* __restrict__ C, int M, int N, int K) {
    extern __shared__ char gsm[];
    const uint32_t sb = smem_u32(gsm);

    const int tid  = threadIdx.x;
    const int warp = tid >> 5, lane = tid & 31;
    const int g = lane >> 2, t = lane & 3;
    const int wm = warp & 3, wn = warp >> 2;
    const int m0 = blockIdx.y * 128;
    const int n0 = blockIdx.x * 128;
    const int NT = K / 32;

    float acc[2][8][4];
#pragma unroll
    for (int mf = 0; mf < 2; mf++)
#pragma unroll
        for (int nf = 0; nf < 8; nf++)
#pragma unroll
            for (int r = 0; r < 4; r++) acc[mf][nf][r] = 0.0f;

    auto prefetch = [&](int s, int kt) {
#pragma unroll
        for (int it = 0; it < 4; it++) {
            int i = tid + it * 256;
            int arr = i >> 9;
            int row = (i >> 2) & 127;
            int ch  = i & 3;
            const __half* src =
                (arr == 0) ? A + (size_t)(m0 + row) * K :
                             W + (size_t)(n0 + row) * K;
            src += kt * 32 + ch * 8;
            uint32_t dst = sb + (uint32_t)(s * GSTG + arr * GARR + row * 80 + ch * 16);
            CP_ASYNC16(dst, src);
        }
    };

    prefetch(0, 0);
    CP_COMMIT();
    prefetch(1, 1);
    CP_COMMIT();

    for (int kt = 0; kt < NT; kt++) {
        if (kt + 1 < NT) CP_WAIT1(); else CP_WAIT0();
        __syncthreads();

        const int st = kt - (kt / 3) * 3;
        const __half* As = (const __half*)(gsm + (size_t)st * GSTG);
        const __half* Ws = As + GARR / 2;

#pragma unroll
        for (int kk = 0; kk < 32; kk += 16) {
            uint32_t a[2][4];
#pragma unroll
            for (int mf = 0; mf < 2; mf++) {
                int r = wm * 32 + mf * 16 + g;
                const __half* p = &As[r * SLD + kk + 2 * t];
                a[mf][0] = *(const uint32_t*)p;
                a[mf][1] = *(const uint32_t*)(p + 8 * SLD);
                a[mf][2] = *(const uint32_t*)(p + 8);
                a[mf][3] = *(const uint32_t*)(p + 8 * SLD + 8);
            }
#pragma unroll
            for (int nf = 0; nf < 8; nf++) {
                const __half* p = &Ws[(wn * 64 + nf * 8 + g) * SLD + kk + 2 * t];
                uint32_t w0 = *(const uint32_t*)p;
                uint32_t w1 = *(const uint32_t*)(p + 8);
#pragma unroll
                for (int mf = 0; mf < 2; mf++)
                    MMA16816(acc[mf][nf], a[mf][0], a[mf][1], a[mf][2], a[mf][3], w0, w1);
            }
        }

        if (kt + 2 < NT) {
            int s2 = (kt + 2) - ((kt + 2) / 3) * 3;
            prefetch(s2, kt + 2);
            CP_COMMIT();
        }
    }

#pragma unroll
    for (int mf = 0; mf < 2; mf++) {
        int r0 = m0 + wm * 32 + mf * 16 + g;
#pragma unroll
        for (int nf = 0; nf < 8; nf++) {
            int col = n0 + wn * 64 + nf * 8 + 2 * t;
            float* p0 = C + (size_t)r0 * N + col;
            float* p1 = C + (size_t)(r0 + 8) * N + col;
            *(float2*)p0 = make_float2(acc[mf][nf][0], acc[mf][nf][1]);
            *(float2*)p1 = make_float2(acc[mf][nf][2], acc[mf][nf][3]);
        }
    }
}

// ============ flash attention: FBQ=64, 128 threads (R16-proven) ==============
#define FBQ 64
#define FBK 64
#define FLD 136
#define ARRB 17408u
#define STG_B (2 * 17408)
#define FA2_SMEM (2 * STG_B)

__global__ __launch_bounds__(128, 2)
void flash_mma_kernel(const __half* __restrict__ Qg,
                      const __half* __restrict__ KH,
                      const __half* __restrict__ VH,
                      __half* __restrict__ Yh) {
    extern __shared__ char smc[];
    const uint32_t sbase = smem_u32(smc);

    const int tid  = threadIdx.x;
    const int w    = tid >> 5, lane = tid & 31;
    const int g    = lane >> 2, t = lane & 3;
    const int qi   = gridDim.x - 1 - blockIdx.x;
    const int bh   = blockIdx.y;
    const int qbase = qi * FBQ;

    const size_t bhoff = (size_t)bh * SEQ * DH;

    uint32_t qf[8][4];
    {
        const __half* q0 = Qg + bhoff + (size_t)(qbase + w * 16 + g) * DH;
        const __half* q1 = q0 + 8 * DH;
#pragma unroll
        for (int kf = 0; kf < 8; kf++) {
            qf[kf][0] = *(const uint32_t*)(q0 + 16 * kf + 2 * t);
            qf[kf][1] = *(const uint32_t*)(q1 + 16 * kf + 2 * t);
            qf[kf][2] = *(const uint32_t*)(q0 + 16 * kf + 2 * t + 8);
            qf[kf][3] = *(const uint32_t*)(q1 + 16 * kf + 2 * t + 8);
        }
    }

    const uint32_t lmK = (uint32_t)(((lane & 7) * FLD + (lane >> 3) * 8) * 2);
    const uint32_t lmV = (uint32_t)((((lane & 7) + ((lane >> 3) & 1) * 8) * FLD
                                     + (lane >> 4) * 8) * 2);

    float m0r = -1e30f, m1r = -1e30f, l0r = 0.0f, l1r = 0.0f;
    float o[16][4];
#pragma unroll
    for (int nf = 0; nf < 16; nf++)
#pragma unroll
        for (int r = 0; r < 4; r++) o[nf][r] = 0.0f;

    const int nkt = qi + 1;

    auto prefetch = [&](int s, int kt) {
        const int kb = kt * FBK;
        const __half* srcs[2] = { KH + bhoff + (size_t)kb * DH,
                                  VH + bhoff + (size_t)kb * DH };
        uint32_t dst0 = sbase + (uint32_t)s * STG_B;
#pragma unroll
        for (int it = 0; it < 16; it++) {
            int i = tid + it * 128;
            int arr = i >> 10, key = (i >> 4) & 63, ch = i & 15;
            const __half* src = srcs[arr] + key * DH + ch * 8;
            uint32_t dst = dst0 + (uint32_t)(arr * ARRB + key * 272 + ch * 16);
            CP_ASYNC16(dst, src);
        }
    };

    prefetch(0, 0);
    CP_COMMIT();

    for (int kt = 0; kt < nkt; kt++) {
        if (kt + 1 < nkt) {
            prefetch((kt + 1) & 1, kt + 1);
            CP_COMMIT();
            CP_WAIT1();
        } else {
            CP_WAIT0();
        }
        __syncthreads();

        const int kbase = kt * FBK;
        {
            const uint32_t stg = sbase + (uint32_t)(kt & 1) * STG_B;

            float s[8][4];
#pragma unroll
            for (int nf = 0; nf < 8; nf++)
#pragma unroll
                for (int r = 0; r < 4; r++) s[nf][r] = 0.0f;

#pragma unroll
            for (int kf2 = 0; kf2 < 4; kf2++) {
#pragma unroll
                for (int nf = 0; nf < 8; nf++) {
                    uint32_t off = (uint32_t)((nf * 8 * FLD + kf2 * 32) * 2);
                    uint32_t k0, k1, k2, k3;
                    LDSM_X4(k0, k1, k2, k3, stg + lmK + off);
                    MMA16816(s[nf], qf[2*kf2][0], qf[2*kf2][1], qf[2*kf2][2], qf[2*kf2][3], k0, k1);
                    MMA16816(s[nf], qf[2*kf2+1][0], qf[2*kf2+1][1], qf[2*kf2+1][2], qf[2*kf2+1][3], k2, k3);
                }
            }

            const int row0 = qbase + w * 16 + g;
            const int row1 = row0 + 8;
            if (kbase + FBK - 1 > qbase + w * 16) {
#pragma unroll
                for (int nf = 0; nf < 8; nf++) {
                    int c0 = kbase + 8 * nf + 2 * t;
                    if (c0 > row0)     s[nf][0] = -1e30f;
                    if (c0 + 1 > row0) s[nf][1] = -1e30f;
                    if (c0 > row1)     s[nf][2] = -1e30f;
                    if (c0 + 1 > row1) s[nf][3] = -1e30f;
                }
            }

            float mx0 = -1e30f, mx1 = -1e30f;
#pragma unroll
            for (int nf = 0; nf < 8; nf++) {
                mx0 = fmaxf(mx0, fmaxf(s[nf][0], s[nf][1]));
                mx1 = fmaxf(mx1, fmaxf(s[nf][2], s[nf][3]));
            }
            mx0 = fmaxf(mx0, __shfl_xor_sync(0xffffffffu, mx0, 1));
            mx0 = fmaxf(mx0, __shfl_xor_sync(0xffffffffu, mx0, 2));
            mx1 = fmaxf(mx1, __shfl_xor_sync(0xffffffffu, mx1, 1));
            mx1 = fmaxf(mx1, __shfl_xor_sync(0xffffffffu, mx1, 2));
            float mn0 = fmaxf(m0r, mx0), mn1 = fmaxf(m1r, mx1);
            float a0 = __expf(m0r - mn0), a1 = __expf(m1r - mn1);
            m0r = mn0; m1r = mn1;
            float rs0 = 0.0f, rs1 = 0.0f;
#pragma unroll
            for (int nf = 0; nf < 8; nf++) {
                s[nf][0] = __expf(s[nf][0] - mn0);
                s[nf][1] = __expf(s[nf][1] - mn0);
                s[nf][2] = __expf(s[nf][2] - mn1);
                s[nf][3] = __expf(s[nf][3] - mn1);
                rs0 += s[nf][0] + s[nf][1];
                rs1 += s[nf][2] + s[nf][3];
            }
            rs0 += __shfl_xor_sync(0xffffffffu, rs0, 1);
            rs0 += __shfl_xor_sync(0xffffffffu, rs0, 2);
            rs1 += __shfl_xor_sync(0xffffffffu, rs1, 1);
            rs1 += __shfl_xor_sync(0xffffffffu, rs1, 2);
            l0r = l0r * a0 + rs0;
            l1r = l1r * a1 + rs1;
#pragma unroll
            for (int nf = 0; nf < 16; nf++) {
                o[nf][0] *= a0; o[nf][1] *= a0;
                o[nf][2] *= a1; o[nf][3] *= a1;
            }

#pragma unroll
            for (int kf = 0; kf < 4; kf++) {
                uint32_t ph[4];
                ph[0] = fp16_pack2(s[2*kf][0],   s[2*kf][1]);
                ph[1] = fp16_pack2(s[2*kf][2],   s[2*kf][3]);
                ph[2] = fp16_pack2(s[2*kf+1][0], s[2*kf+1][1]);
                ph[3] = fp16_pack2(s[2*kf+1][2], s[2*kf+1][3]);
                uint32_t voff = (uint32_t)((kf * 16 * FLD) * 2);
#pragma unroll
                for (int nf2 = 0; nf2 < 8; nf2++) {
                    uint32_t off = voff + (uint32_t)(nf2 * 32);
                    uint32_t v0, v1, v2, v3;
                    LDSM_X4T(v0, v1, v2, v3, stg + ARRB + lmV + off);
                    MMA16816(o[2*nf2],   ph[0], ph[1], ph[2], ph[3], v0, v1);
                    MMA16816(o[2*nf2+1], ph[0], ph[1], ph[2], ph[3], v2, v3);
                }
            }
        }
        __syncthreads();
    }

    const int b = bh >> 4, h = bh & 15;
    const int row0 = qbase + w * 16 + g;
    const float inv0 = 1.0f / l0r, inv1 = 1.0f / l1r;
    size_t y0off = ((size_t)(b * SEQ + row0)) * NEMBD + h * DH;
    size_t y1off = ((size_t)(b * SEQ + row0 + 8)) * NEMBD + h * DH;
#pragma unroll
    for (int nf = 0; nf < 16; nf++) {
        int col = 8 * nf + 2 * t;
        *(uint32_t*)(Yh + y0off + col) = fp16_pack2(o[nf][0] * inv0, o[nf][1] * inv0);
        *(uint32_t*)(Yh + y1off + col) = fp16_pack2(o[nf][2] * inv1, o[nf][3] * inv1);
    }
}

// ================= launch =====================================================
extern "C" void kernel_launch(void* const* d_in, const int* in_sizes, int n_in,
                              void* d_out, int out_size) {
    const float* x      = (const float*)d_in[0];
    const float* w_qkv  = (const float*)d_in[1];
    const float* w_proj = (const float*)d_in[2];
    float* out = (float*)d_out;

    float *gc, *gs;
    __half *qh, *kh, *vh, *xh, *wq, *wp, *yh;
    cudaGetSymbolAddress((void**)&qh, g_qh);
    cudaGetSymbolAddress((void**)&kh, g_kh);
    cudaGetSymbolAddress((void**)&vh, g_vh);
    cudaGetSymbolAddress((void**)&xh, g_xh);
    cudaGetSymbolAddress((void**)&wq, g_wq);
    cudaGetSymbolAddress((void**)&wp, g_wp);
    cudaGetSymbolAddress((void**)&yh, g_yh);
    cudaGetSymbolAddress((void**)&gc, g_cos);
    cudaGetSymbolAddress((void**)&gs, g_sin);

    // 1) RoPE tables + fused operand conversions
    rope_table_kernel<<<(SEQ * 64 + 255) / 256, 256>>>(gc, gs);
    cvt_all_kernel<<<(unsigned)((CVT_TOT + 255) / 256), 256>>>(
        x, w_qkv, w_proj, xh, wq, wp);

    // 2) QKV projection + fused RoPE (3-stage pipeline)
    cudaFuncSetAttribute(gemm_qkv_rope_kernel,
                         cudaFuncAttributeMaxDynamicSharedMemorySize, GEMM_SMEM);
    gemm_qkv_rope_kernel<<<dim3(QKV_N / 128, MROWS / 128), 256, GEMM_SMEM>>>(
        xh, wq, gc, gs, qh, kh, vh);

    // 3) flash attention (FBQ=64, 2 CTAs/SM) -> y fp16
    cudaFuncSetAttribute(flash_mma_kernel,
                         cudaFuncAttributeMaxDynamicSharedMemorySize, FA2_SMEM);
    flash_mma_kernel<<<dim3(SEQ / FBQ, BHN), 128, FA2_SMEM>>>(
        qh, kh, vh, yh);

    // 4) output projection (3-stage pipeline, fp32 out)
    cudaFuncSetAttribute(gemm_fp16_kernel,
                         cudaFuncAttributeMaxDynamicSharedMemorySize, GEMM_SMEM);
    gemm_fp16_kernel<<<dim3(NEMBD / 128, MROWS / 128), 256, GEMM_SMEM>>>(
        yh, wp, out, MROWS, NEMBD, NEMBD);
}